// round 14
// baseline (speedup 1.0000x reference)
#include <cuda_runtime.h>
#include <cuda_bf16.h>
#include <mma.h>
#include <cstddef>

using namespace nvcuda;
typedef __nv_bfloat16 bf16;

#define D    512
#define H    8
#define DK   64
#define TT   128
#define BBATCH 8
#define NL   6
#define VV   32000
#define FF   2048
#define MROWS (BBATCH*TT)
#define MD   (MROWS*D)

#define N_EA  (NL*4*D*D)
#define N_EF1 (NL*D*FF)
#define N_EF2 (NL*FF*D)
#define N_DA  (NL*8*D*D)
#define N_DF1 (NL*D*FF)
#define N_DF2 (NL*FF*D)
#define N_EMB (VV*D)
#define OFF_EA   0
#define OFF_EF1  (OFF_EA + N_EA)
#define OFF_EF2  (OFF_EF1 + N_EF1)
#define OFF_DA   (OFF_EF2 + N_EF2)
#define OFF_DF1  (OFF_DA + N_DA)
#define OFF_DF2  (OFF_DF1 + N_DF1)
#define OFF_EMB  (OFF_DF2 + N_DF2)
#define WPOOL_N  (OFF_EMB + N_EMB)

__device__ float g_x  [MD];
__device__ float g_x2 [MD];
__device__ bf16  g_qkv[3*MD];
__device__ bf16  g_hb [MD];
__device__ bf16  g_hb2[MD];
__device__ bf16  g_aob[MD];
__device__ bf16  g_memb[MD];
__device__ bf16  g_ffnb[MROWS*FF];
__device__ bf16  g_kvc[2*NL*MD];
__device__ bf16  g_wpool[WPOOL_N];

// ---------------- PDL ----------------
__device__ __forceinline__ void gdc_wait() {
    asm volatile("griddepcontrol.wait;" ::: "memory");
}

// ---------------- cp.async helpers ----------------
__device__ __forceinline__ void cpa16(void* dst, const void* src) {
    unsigned sdst = (unsigned)__cvta_generic_to_shared(dst);
    asm volatile("cp.async.cg.shared.global [%0], [%1], 16;\n" :: "r"(sdst), "l"(src));
}
__device__ __forceinline__ void cpa_commit() { asm volatile("cp.async.commit_group;\n"); }
template<int N>
__device__ __forceinline__ void cpa_wait() { asm volatile("cp.async.wait_group %0;\n" :: "n"(N)); }

// ---------------- merged fp32 -> bf16 conversion ----------------
#define C4_0 (N_EA/4)
#define C4_1 (C4_0 + N_EF1/4)
#define C4_2 (C4_1 + N_EF2/4)
#define C4_3 (C4_2 + N_DA/4)
#define C4_4 (C4_3 + N_DF1/4)
#define C4_5 (C4_4 + N_DF2/4)
#define C4_6 (C4_5 + N_EMB/4)

__global__ void cvt_all_kernel(const float* __restrict__ s0, const float* __restrict__ s1,
                               const float* __restrict__ s2, const float* __restrict__ s3,
                               const float* __restrict__ s4, const float* __restrict__ s5,
                               const float* __restrict__ s6, bf16* __restrict__ pool) {
    gdc_wait();
    int i = blockIdx.x * blockDim.x + threadIdx.x;
    if (i >= C4_6) return;
    const float* s;
    int off;
    if      (i < C4_0) { s = s0; off = i; }
    else if (i < C4_1) { s = s1; off = i - C4_0; }
    else if (i < C4_2) { s = s2; off = i - C4_1; }
    else if (i < C4_3) { s = s3; off = i - C4_2; }
    else if (i < C4_4) { s = s4; off = i - C4_3; }
    else if (i < C4_5) { s = s5; off = i - C4_4; }
    else               { s = s6; off = i - C4_5; }
    float4 v = reinterpret_cast<const float4*>(s)[off];
    __nv_bfloat162* o = reinterpret_cast<__nv_bfloat162*>(pool) + 2 * (size_t)i;
    o[0] = __floats2bfloat162_rn(v.x, v.y);
    o[1] = __floats2bfloat162_rn(v.z, v.w);
}

// ---------------- embedding + LN fused, both stacks in one launch ----------------
__global__ __launch_bounds__(256) void embed2_kernel(
        const int* __restrict__ tokA, const int* __restrict__ tokB,
        const float* __restrict__ tok_emb, const float* __restrict__ pos_emb,
        const float* __restrict__ gA, const float* __restrict__ bA,
        const float* __restrict__ gB, const float* __restrict__ bB,
        float* __restrict__ xA, float* __restrict__ xB,
        bf16* __restrict__ hA, bf16* __restrict__ hB) {
    gdc_wait();
    int set = blockIdx.y;
    const int*   tok = set ? tokB : tokA;
    const float* g   = set ? gB : gA;
    const float* b   = set ? bB : bA;
    float*       xo  = set ? xB : xA;
    bf16*        ho  = set ? hB : hA;

    int row  = blockIdx.x * 8 + (threadIdx.x >> 5);
    int lane = threadIdx.x & 31;
    int t = row % TT;
    const float4* te = reinterpret_cast<const float4*>(tok_emb + (size_t)tok[row] * D);
    const float4* pe = reinterpret_cast<const float4*>(pos_emb + (size_t)t * D);
    float4* x4 = reinterpret_cast<float4*>(xo + (size_t)row * D);

    float4 v[4];
    float s = 0.f;
    #pragma unroll
    for (int j = 0; j < 4; j++) {
        int c = lane + j * 32;
        float4 a = te[c], p = pe[c];
        v[j].x = a.x + p.x; v[j].y = a.y + p.y; v[j].z = a.z + p.z; v[j].w = a.w + p.w;
        x4[c] = v[j];
        s += v[j].x + v[j].y + v[j].z + v[j].w;
    }
    #pragma unroll
    for (int o = 16; o; o >>= 1) s += __shfl_xor_sync(0xffffffffu, s, o);
    float mu = s * (1.f / D);

    float var = 0.f;
    #pragma unroll
    for (int j = 0; j < 4; j++) {
        float a0 = v[j].x - mu, a1 = v[j].y - mu, a2 = v[j].z - mu, a3 = v[j].w - mu;
        var += a0 * a0 + a1 * a1 + a2 * a2 + a3 * a3;
    }
    #pragma unroll
    for (int o = 16; o; o >>= 1) var += __shfl_xor_sync(0xffffffffu, var, o);
    float inv = rsqrtf(var * (1.f / D) + 1e-6f);

    const float4* g4 = reinterpret_cast<const float4*>(g);
    const float4* b4 = reinterpret_cast<const float4*>(b);
    uint2* o8 = reinterpret_cast<uint2*>(ho + (size_t)row * D);
    #pragma unroll
    for (int j = 0; j < 4; j++) {
        int c = lane + j * 32;
        float4 gg = g4[c], bb = b4[c];
        float r0 = (v[j].x - mu) * inv * gg.x + bb.x;
        float r1 = (v[j].y - mu) * inv * gg.y + bb.y;
        float r2 = (v[j].z - mu) * inv * gg.z + bb.z;
        float r3 = (v[j].w - mu) * inv * gg.w + bb.w;
        __nv_bfloat162 lo = __floats2bfloat162_rn(r0, r1);
        __nv_bfloat162 hi = __floats2bfloat162_rn(r2, r3);
        uint2 pk; pk.x = *reinterpret_cast<unsigned*>(&lo); pk.y = *reinterpret_cast<unsigned*>(&hi);
        o8[c] = pk;
    }
}

// ---------------- layernorm: warp per row, 8 rows/block ----------------
__global__ __launch_bounds__(256) void ln_kernel(const float* __restrict__ x,
                          const float* __restrict__ g,
                          const float* __restrict__ b,
                          bf16* __restrict__ out) {
    gdc_wait();
    int row  = blockIdx.x * 8 + (threadIdx.x >> 5);
    int lane = threadIdx.x & 31;
    const float4* xr = reinterpret_cast<const float4*>(x + (size_t)row * D);

    float4 v[4];
    float s = 0.f;
    #pragma unroll
    for (int j = 0; j < 4; j++) {
        v[j] = xr[lane + j * 32];
        s += v[j].x + v[j].y + v[j].z + v[j].w;
    }
    #pragma unroll
    for (int o = 16; o; o >>= 1) s += __shfl_xor_sync(0xffffffffu, s, o);
    float mu = s * (1.f / D);

    float var = 0.f;
    #pragma unroll
    for (int j = 0; j < 4; j++) {
        float a0 = v[j].x - mu, a1 = v[j].y - mu, a2 = v[j].z - mu, a3 = v[j].w - mu;
        var += a0 * a0 + a1 * a1 + a2 * a2 + a3 * a3;
    }
    #pragma unroll
    for (int o = 16; o; o >>= 1) var += __shfl_xor_sync(0xffffffffu, var, o);
    float inv = rsqrtf(var * (1.f / D) + 1e-6f);

    const float4* g4 = reinterpret_cast<const float4*>(g);
    const float4* b4 = reinterpret_cast<const float4*>(b);
    uint2* o8 = reinterpret_cast<uint2*>(out + (size_t)row * D);
    #pragma unroll
    for (int j = 0; j < 4; j++) {
        int c = lane + j * 32;
        float4 gg = g4[c], bb = b4[c];
        float r0 = (v[j].x - mu) * inv * gg.x + bb.x;
        float r1 = (v[j].y - mu) * inv * gg.y + bb.y;
        float r2 = (v[j].z - mu) * inv * gg.z + bb.z;
        float r3 = (v[j].w - mu) * inv * gg.w + bb.w;
        __nv_bfloat162 lo = __floats2bfloat162_rn(r0, r1);
        __nv_bfloat162 hi = __floats2bfloat162_rn(r2, r3);
        uint2 pk; pk.x = *reinterpret_cast<unsigned*>(&lo); pk.y = *reinterpret_cast<unsigned*>(&hi);
        o8[c] = pk;
    }
}

// ---------------- bf16 GEMM, 2-stage cp.async BK=32 (B prefetched before gdc_wait) ----------------
#define ASTR 48
#define BSTR0 72
#define BSTR1 48
#define BSZ (64*BSTR1)

template<int TB, int OB, int MT>
__global__ __launch_bounds__(256) void wgemm(
        const bf16* __restrict__ Ag, const bf16* __restrict__ Bg,
        const float* __restrict__ bias, const float* __restrict__ res,
        void* __restrict__ Cv, int M, int N, int K, int relu,
        size_t sA, size_t sB, size_t sBias, size_t sC) {
    constexpr int WSM = MT / 32;
    constexpr int WSN = 8 / WSM;
    constexpr int NFR = 64 / (WSN * 16);
    constexpr int ASZ = MT * ASTR;

    const int z = blockIdx.z;
    const bf16* A = Ag + (size_t)z * sA;
    const bf16* B = Bg + (size_t)z * sB;
    const float* bi = bias ? bias + (size_t)z * sBias : nullptr;

    __shared__ __align__(16) char smem_raw[36864];
    bf16*  Abase = reinterpret_cast<bf16*>(smem_raw);
    bf16*  Bbase = Abase + 2 * ASZ;
    float* Cs    = reinterpret_cast<float*>(smem_raw);

    const int tid  = threadIdx.x;
    const int warp = tid >> 5;
    const int wm   = warp % WSM;
    const int wn   = warp / WSM;
    const int wnoff = wn * 16 * NFR;
    const int m0 = blockIdx.y * MT, n0 = blockIdx.x * 64;

    wmma::fragment<wmma::accumulator, 16, 16, 16, float> acc[2][NFR];
    #pragma unroll
    for (int i = 0; i < 2; i++)
        #pragma unroll
        for (int j = 0; j < NFR; j++) wmma::fill_fragment(acc[i][j], 0.f);

    auto load_A = [&](int s, int k0) {
        bf16* As = Abase + s * ASZ;
        #pragma unroll
        for (int it = 0; it < MT / 64; it++) {
            int chunk = tid + it * 256;
            int r = chunk >> 2, c = (chunk & 3) << 3;
            cpa16(&As[r * ASTR + c], &A[(size_t)(m0 + r) * K + k0 + c]);
        }
    };
    auto load_B = [&](int s, int k0) {
        bf16* Bs = Bbase + s * BSZ;
        if (TB == 0) {
            int r = tid >> 3, c = (tid & 7) << 3;
            cpa16(&Bs[r * BSTR0 + c], &B[(size_t)(k0 + r) * N + n0 + c]);
        } else {
            int r = tid >> 2, c = (tid & 3) << 3;
            cpa16(&Bs[r * BSTR1 + c], &B[(size_t)(n0 + r) * K + k0 + c]);
        }
    };

    auto compute_stage = [&](int s) {
        bf16* As = Abase + s * ASZ;
        bf16* Bs = Bbase + s * BSZ;
        #pragma unroll
        for (int kk = 0; kk < 32; kk += 16) {
            wmma::fragment<wmma::matrix_a, 16, 16, 16, bf16, wmma::row_major> a0, a1;
            wmma::load_matrix_sync(a0, &As[(wm * 32 +  0) * ASTR + kk], ASTR);
            wmma::load_matrix_sync(a1, &As[(wm * 32 + 16) * ASTR + kk], ASTR);
            #pragma unroll
            for (int j = 0; j < NFR; j++) {
                if (TB == 0) {
                    wmma::fragment<wmma::matrix_b, 16, 16, 16, bf16, wmma::row_major> bf;
                    wmma::load_matrix_sync(bf, &Bs[kk * BSTR0 + wnoff + j * 16], BSTR0);
                    wmma::mma_sync(acc[0][j], a0, bf, acc[0][j]);
                    wmma::mma_sync(acc[1][j], a1, bf, acc[1][j]);
                } else {
                    wmma::fragment<wmma::matrix_b, 16, 16, 16, bf16, wmma::col_major> bf;
                    wmma::load_matrix_sync(bf, &Bs[(wnoff + j * 16) * BSTR1 + kk], BSTR1);
                    wmma::mma_sync(acc[0][j], a0, bf, acc[0][j]);
                    wmma::mma_sync(acc[1][j], a1, bf, acc[1][j]);
                }
            }
        }
    };

    // prologue: prefetch weights (independent) before waiting on predecessor
    load_B(0, 0);
    gdc_wait();
    load_A(0, 0);
    cpa_commit();

    const int KT = K >> 5;
    for (int kt = 0; kt < KT; kt++) {
        if (kt + 1 < KT) {
            load_B((kt + 1) & 1, (kt + 1) << 5);
            load_A((kt + 1) & 1, (kt + 1) << 5);
            cpa_commit(); cpa_wait<1>();
        } else {
            cpa_wait<0>();
        }
        __syncthreads();
        compute_stage(kt & 1);
        __syncthreads();
    }

    #pragma unroll
    for (int i = 0; i < 2; i++)
        #pragma unroll
        for (int j = 0; j < NFR; j++)
            wmma::store_matrix_sync(&Cs[(wm * 32 + i * 16) * 72 + wnoff + j * 16],
                                    acc[i][j], 72, wmma::mem_row_major);
    __syncthreads();

    #pragma unroll
    for (int it = 0; it < MT / 4; it++) {
        int idx = tid + it * 256;
        int r = idx >> 6, c = idx & 63;
        int m = m0 + r, n = n0 + c;
        float val = Cs[r * 72 + c];
        if (bi)   val += bi[n];
        if (relu) val = fmaxf(val, 0.f);
        if (OB) {
            reinterpret_cast<bf16*>(Cv)[(size_t)z * sC + (size_t)m * N + n] = __float2bfloat16(val);
        } else {
            float* C = reinterpret_cast<float*>(Cv) + (size_t)z * sC;
            if (res) val += res[(size_t)m * N + n];
            C[(size_t)m * N + n] = val;
        }
    }
}

// ---------------- 128x128 bf16 GEMM (BK=32, static smem; kvmode; B prefetch) ----------------
#define A2STR 40
#define B2STR0 136
#define B2STR1 40

template<int TB, int EPI>
__global__ __launch_bounds__(256) void wgemm2(
        const bf16* __restrict__ Ag, const bf16* __restrict__ Bg,
        const float* __restrict__ bias, void* __restrict__ Cv,
        int M, int N, int K, int relu,
        size_t sA, size_t sB, size_t sBias, size_t sC, int kvmode) {
    constexpr int BST   = TB ? B2STR1 : B2STR0;
    constexpr int BROWS = TB ? 128 : 32;
    constexpr int A2SZ  = 128 * A2STR;
    constexpr int B2SZ  = BROWS * BST;
    constexpr int STG2  = A2SZ + B2SZ;

    const int z = blockIdx.z;
    size_t zA, zB, zBias, zC;
    if (kvmode) {
        int layer = z >> 1, kv = z & 1;
        zA = 0;
        zB = ((size_t)layer * 8 + 5 + kv) * (size_t)D * D;
        zBias = ((size_t)layer * 8 + 5 + kv) * D;
        zC = (size_t)(kv * NL + layer) * sC;
    } else {
        zA = (size_t)z * sA; zB = (size_t)z * sB;
        zBias = (size_t)z * sBias; zC = (size_t)z * sC;
    }
    const bf16* A = Ag + zA;
    const bf16* B = Bg + zB;
    const float* bi = bias ? bias + zBias : nullptr;

    __shared__ __align__(16) bf16 sm[2 * STG2];
    float* Cs = reinterpret_cast<float*>(sm);

    const int tid  = threadIdx.x;
    const int warp = tid >> 5;
    const int wm   = warp & 3;
    const int wn   = warp >> 2;
    const int m0 = blockIdx.y * 128, n0 = blockIdx.x * 128;

    wmma::fragment<wmma::accumulator, 16, 16, 16, float> acc[2][4];
    #pragma unroll
    for (int i = 0; i < 2; i++)
        #pragma unroll
        for (int j = 0; j < 4; j++) wmma::fill_fragment(acc[i][j], 0.f);

    auto load_A = [&](int s, int k0) {
        bf16* As = sm + s * STG2;
        #pragma unroll
        for (int it = 0; it < 2; it++) {
            int chunk = tid + it * 256;
            int r = chunk >> 2, c = (chunk & 3) << 3;
            cpa16(&As[r * A2STR + c], &A[(size_t)(m0 + r) * K + k0 + c]);
        }
    };
    auto load_B = [&](int s, int k0) {
        bf16* Bs = sm + s * STG2 + A2SZ;
        if (TB == 0) {
            #pragma unroll
            for (int it = 0; it < 2; it++) {
                int chunk = tid + it * 256;
                int r = chunk >> 4, c = (chunk & 15) << 3;
                cpa16(&Bs[r * B2STR0 + c], &B[(size_t)(k0 + r) * N + n0 + c]);
            }
        } else {
            #pragma unroll
            for (int it = 0; it < 2; it++) {
                int chunk = tid + it * 256;
                int r = chunk >> 2, c = (chunk & 3) << 3;
                cpa16(&Bs[r * B2STR1 + c], &B[(size_t)(n0 + r) * K + k0 + c]);
            }
        }
    };

    auto compute_stage = [&](int s) {
        bf16* As = sm + s * STG2;
        bf16* Bs = As + A2SZ;
        #pragma unroll
        for (int kk = 0; kk < 32; kk += 16) {
            wmma::fragment<wmma::matrix_a, 16, 16, 16, bf16, wmma::row_major> a0, a1;
            wmma::load_matrix_sync(a0, &As[(wm * 32 +  0) * A2STR + kk], A2STR);
            wmma::load_matrix_sync(a1, &As[(wm * 32 + 16) * A2STR + kk], A2STR);
            #pragma unroll
            for (int j = 0; j < 4; j++) {
                if (TB == 0) {
                    wmma::fragment<wmma::matrix_b, 16, 16, 16, bf16, wmma::row_major> bf;
                    wmma::load_matrix_sync(bf, &Bs[kk * B2STR0 + wn * 64 + j * 16], B2STR0);
                    wmma::mma_sync(acc[0][j], a0, bf, acc[0][j]);
                    wmma::mma_sync(acc[1][j], a1, bf, acc[1][j]);
                } else {
                    wmma::fragment<wmma::matrix_b, 16, 16, 16, bf16, wmma::col_major> bf;
                    wmma::load_matrix_sync(bf, &Bs[(wn * 64 + j * 16) * B2STR1 + kk], B2STR1);
                    wmma::mma_sync(acc[0][j], a0, bf, acc[0][j]);
                    wmma::mma_sync(acc[1][j], a1, bf, acc[1][j]);
                }
            }
        }
    };

    load_B(0, 0);
    gdc_wait();
    load_A(0, 0);
    cpa_commit();

    const int KT = K >> 5;
    for (int kt = 0; kt < KT; kt++) {
        if (kt + 1 < KT) {
            load_B((kt + 1) & 1, (kt + 1) << 5);
            load_A((kt + 1) & 1, (kt + 1) << 5);
            cpa_commit(); cpa_wait<1>();
        } else {
            cpa_wait<0>();
        }
        __syncthreads();
        compute_stage(kt & 1);
        __syncthreads();
    }

    if (EPI == 0) {
        float* C = reinterpret_cast<float*>(Cv) + zC;
        #pragma unroll
        for (int i = 0; i < 2; i++)
            #pragma unroll
            for (int j = 0; j < 4; j++)
                wmma::store_matrix_sync(
                    &C[(size_t)(m0 + wm * 32 + i * 16) * N + n0 + wn * 64 + j * 16],
                    acc[i][j], N, wmma::mem_row_major);
    } else {
        bf16* Co = reinterpret_cast<bf16*>(Cv) + zC;
        #pragma unroll
        for (int hh = 0; hh < 2; hh++) {
            if ((wm >> 1) == hh) {
                #pragma unroll
                for (int i = 0; i < 2; i++)
                    #pragma unroll
                    for (int j = 0; j < 4; j++)
                        wmma::store_matrix_sync(
                            &Cs[((wm & 1) * 32 + i * 16) * 136 + wn * 64 + j * 16],
                            acc[i][j], 136, wmma::mem_row_major);
            }
            __syncthreads();
            #pragma unroll
            for (int it = 0; it < 32; it++) {
                int idx = tid + it * 256;
                int r = idx >> 7, c = idx & 127;
                int m = m0 + hh * 64 + r, n = n0 + c;
                float val = Cs[r * 136 + c];
                if (bi)   val += bi[n];
                if (relu) val = fmaxf(val, 0.f);
                Co[(size_t)m * N + n] = __float2bfloat16(val);
            }
            __syncthreads();
        }
    }
}

// ---------------- fused flash attention: Q-tile 32, async K/V loads ----------------
#define FA_SMEM 58368

__global__ __launch_bounds__(256) void flash_kernel(
        const bf16* __restrict__ Q, const bf16* __restrict__ Kp, const bf16* __restrict__ Vp,
        const int* __restrict__ toks, int causal, bf16* __restrict__ out) {
    extern __shared__ __align__(16) char sm[];
    bf16*  Qs = reinterpret_cast<bf16*>(sm);
    bf16*  Ks = Qs + 32 * 72;
    bf16*  Vs = Ks + 128 * 72;
    float* S  = reinterpret_cast<float*>(sm + 41472);
    bf16*  Pb = reinterpret_cast<bf16*>(sm);
    __shared__ int msk[TT];

    const int q0 = blockIdx.x * 32;
    const int h  = blockIdx.y;
    const int b  = blockIdx.z;
    const int tid = threadIdx.x, warp = tid >> 5, lane = tid & 31;

    // toks is a harness input — safe to read before the PDL wait
    int mv = 0;
    if (tid < TT) mv = (toks[b * TT + tid] == 1);
    gdc_wait();

    #pragma unroll
    for (int it = 0; it < 4; it++) {
        int ch = tid + it * 256;
        int r = ch >> 3, c = (ch & 7) << 3;
        cpa16(&Ks[r * 72 + c], &Kp[(size_t)(b * TT + r) * D + h * DK + c]);
    }
    cpa_commit();
    #pragma unroll
    for (int it = 0; it < 4; it++) {
        int ch = tid + it * 256;
        int r = ch >> 3, c = (ch & 7) << 3;
        cpa16(&Vs[r * 72 + c], &Vp[(size_t)(b * TT + r) * D + h * DK + c]);
    }
    cpa_commit();
    {
        int r = tid >> 3, c = (tid & 7) << 3;
        *reinterpret_cast<uint4*>(&Qs[r * 72 + c]) =
            *reinterpret_cast<const uint4*>(&Q[(size_t)(b * TT + q0 + r) * D + h * DK + c]);
    }
    if (tid < TT) msk[tid] = mv;
    cpa_wait<1>();
    __syncthreads();

    {
        int wm = warp & 1, wn = warp >> 1;
        #pragma unroll
        for (int n = 0; n < 2; n++) {
            wmma::fragment<wmma::accumulator, 16, 16, 16, float> acc;
            wmma::fill_fragment(acc, 0.f);
            #pragma unroll
            for (int kk = 0; kk < 4; kk++) {
                wmma::fragment<wmma::matrix_a, 16, 16, 16, bf16, wmma::row_major> a;
                wmma::fragment<wmma::matrix_b, 16, 16, 16, bf16, wmma::col_major> bb;
                wmma::load_matrix_sync(a, &Qs[(wm * 16) * 72 + kk * 16], 72);
                wmma::load_matrix_sync(bb, &Ks[(wn * 32 + n * 16) * 72 + kk * 16], 72);
                wmma::mma_sync(acc, a, bb, acc);
            }
            wmma::store_matrix_sync(&S[(wm * 16) * 132 + wn * 32 + n * 16], acc, 132,
                                    wmma::mem_row_major);
        }
    }
    __syncthreads();

    for (int rr = 0; rr < 4; rr++) {
        int r = warp * 4 + rr;
        int qg = q0 + r;
        float v[4];
        #pragma unroll
        for (int j = 0; j < 4; j++) {
            int col = lane + j * 32;
            float s = S[r * 132 + col] * 0.125f;
            if (msk[col] || (causal && col > qg)) s = -1e30f;
            v[j] = s;
        }
        float m = fmaxf(fmaxf(v[0], v[1]), fmaxf(v[2], v[3]));
        #pragma unroll
        for (int o = 16; o; o >>= 1) m = fmaxf(m, __shfl_xor_sync(0xffffffffu, m, o));
        float e[4], sum = 0.f;
        #pragma unroll
        for (int j = 0; j < 4; j++) { e[j] = __expf(v[j] - m); sum += e[j]; }
        #pragma unroll
        for (int o = 16; o; o >>= 1) sum += __shfl_xor_sync(0xffffffffu, sum, o);
        float inv = __frcp_rn(sum);
        #pragma unroll
        for (int j = 0; j < 4; j++)
            Pb[r * 136 + lane + j * 32] = __float2bfloat16(e[j] * inv);
    }
    cpa_wait<0>();
    __syncthreads();

    {
        int wm = warp & 1, wn = warp >> 1;
        wmma::fragment<wmma::accumulator, 16, 16, 16, float> acc;
        wmma::fill_fragment(acc, 0.f);
        #pragma unroll
        for (int kk = 0; kk < 8; kk++) {
            wmma::fragment<wmma::matrix_a, 16, 16, 16, bf16, wmma::row_major> a;
            wmma::fragment<wmma::matrix_b, 16, 16, 16, bf16, wmma::row_major> bb;
            wmma::load_matrix_sync(a, &Pb[(wm * 16) * 136 + kk * 16], 136);
            wmma::load_matrix_sync(bb, &Vs[(kk * 16) * 72 + wn * 16], 72);
            wmma::mma_sync(acc, a, bb, acc);
        }
        wmma::store_matrix_sync(&S[(wm * 16) * 132 + wn * 16], acc, 132,
                                wmma::mem_row_major);
    }
    __syncthreads();

    for (int idx = tid; idx < 32 * 64; idx += 256) {
        int r = idx >> 6, c = idx & 63;
        out[(size_t)(b * TT + q0 + r) * D + h * DK + c] = __float2bfloat16(S[r * 132 + c]);
    }
}

// ---------------- log_softmax: row cached in dynamic smem ----------------
#define LS_SMEM (VV*4)

__global__ __launch_bounds__(512) void logsoftmax_kernel(float* __restrict__ logits) {
    gdc_wait();
    extern __shared__ float xs[];
    int row = blockIdx.x;
    float* x = logits + (size_t)row * VV;
    __shared__ float shm[512], shs[512];
    int tid = threadIdx.x;

    float m = -1e30f, s = 0.f;
    for (int i = tid; i < VV / 4; i += 512) {
        float4 v = reinterpret_cast<const float4*>(x)[i];
        reinterpret_cast<float4*>(xs)[i] = v;
        float cm = fmaxf(fmaxf(v.x, v.y), fmaxf(v.z, v.w));
        if (cm > m) { s *= __expf(m - cm); m = cm; }
        s += __expf(v.x - m) + __expf(v.y - m) + __expf(v.z - m) + __expf(v.w - m);
    }
    shm[tid] = m; shs[tid] = s; __syncthreads();
    for (int o = 256; o; o >>= 1) {
        if (tid < o) {
            float m2 = shm[tid + o], s2 = shs[tid + o];
            float mn = fmaxf(shm[tid], m2);
            shs[tid] = shs[tid] * __expf(shm[tid] - mn) + s2 * __expf(m2 - mn);
            shm[tid] = mn;
        }
        __syncthreads();
    }
    float lse = shm[0] + logf(shs[0]);

    for (int i = tid; i < VV / 4; i += 512) {
        float4 v = reinterpret_cast<float4*>(xs)[i];
        v.x -= lse; v.y -= lse; v.z -= lse; v.w -= lse;
        reinterpret_cast<float4*>(x)[i] = v;
    }
}

// ---------------- host: PDL launch helper ----------------
static void launch_pdl(const void* func, dim3 grid, dim3 block, size_t smem, void** args) {
    cudaLaunchAttribute attr;
    attr.id = cudaLaunchAttributeProgrammaticStreamSerialization;
    attr.val.programmaticStreamSerializationAllowed = 1;
    cudaLaunchConfig_t cfg = {};
    cfg.gridDim = grid;
    cfg.blockDim = block;
    cfg.dynamicSmemBytes = smem;
    cfg.stream = 0;
    cfg.attrs = &attr;
    cfg.numAttrs = 1;
    cudaLaunchKernelExC(&cfg, func, args);
}

static void G(const bf16* A, const bf16* B, const float* bias, const float* res,
              void* C, int M, int N, int K, int relu, int tb, int ob, int mt, int batch,
              size_t sA, size_t sB, size_t sBias, size_t sC) {
    dim3 grid(N / 64, M / mt, batch);
    void* args[] = {&A, &B, &bias, &res, &C, &M, &N, &K, &relu, &sA, &sB, &sBias, &sC};
    const void* f;
    if (tb)                    f = (const void*)wgemm<1, 0, 128>;
    else if (ob && mt == 128)  f = (const void*)wgemm<0, 1, 128>;
    else if (ob)               f = (const void*)wgemm<0, 1, 64>;
    else                       f = (const void*)wgemm<0, 0, 64>;
    launch_pdl(f, grid, dim3(256), 0, args);
}

static void G2(int variant, dim3 grid, const bf16* A, const bf16* B, const float* bias,
               void* C, int M, int N, int K, int relu,
               size_t sA, size_t sB, size_t sBias, size_t sC, int kvmode) {
    void* args[] = {&A, &B, &bias, &C, &M, &N, &K, &relu, &sA, &sB, &sBias, &sC, &kvmode};
    const void* f = variant ? (const void*)wgemm2<1, 0> : (const void*)wgemm2<0, 1>;
    launch_pdl(f, grid, dim3(256), 0, args);
}

static void FL(dim3 grid, const bf16* Q, const bf16* Kp, const bf16* Vp,
               const int* toks, int causal, bf16* out) {
    void* args[] = {&Q, &Kp, &Vp, &toks, &causal, &out};
    launch_pdl((const void*)flash_kernel, grid, dim3(256), FA_SMEM, args);
}

static void LN(const float* x, const float* g, const float* b, bf16* out) {
    void* args[] = {&x, &g, &b, &out};
    launch_pdl((const void*)ln_kernel, dim3(MROWS / 8), dim3(256), 0, args);
}

extern "C" void kernel_launch(void* const* d_in, const int* in_sizes, int n_in,
                              void* d_out, int out_size) {
    const int*   src        = (const int*)  d_in[0];
    const int*   tgt        = (const int*)  d_in[1];
    const float* tok_emb    = (const float*)d_in[2];
    const float* pos_emb    = (const float*)d_in[3];
    const float* enc_attn_w = (const float*)d_in[4];
    const float* enc_attn_b = (const float*)d_in[5];
    const float* enc_ffn_w1 = (const float*)d_in[6];
    const float* enc_ffn_b1 = (const float*)d_in[7];
    const float* enc_ffn_w2 = (const float*)d_in[8];
    const float* enc_ffn_b2 = (const float*)d_in[9];
    const float* enc_ln     = (const float*)d_in[10];
    const float* enc_fln    = (const float*)d_in[11];
    const float* dec_attn_w = (const float*)d_in[12];
    const float* dec_attn_b = (const float*)d_in[13];
    const float* dec_ffn_w1 = (const float*)d_in[14];
    const float* dec_ffn_b1 = (const float*)d_in[15];
    const float* dec_ffn_w2 = (const float*)d_in[16];
    const float* dec_ffn_b2 = (const float*)d_in[17];
    const float* dec_ln     = (const float*)d_in[18];
    const float* dec_fln    = (const float*)d_in[19];
    float* out = (float*)d_out;

    float *x, *x2;
    bf16 *qkv, *hb, *hb2, *aob, *memb, *ffnb, *kvc, *wp;
    cudaGetSymbolAddress((void**)&x,    g_x);
    cudaGetSymbolAddress((void**)&x2,   g_x2);
    cudaGetSymbolAddress((void**)&qkv,  g_qkv);
    cudaGetSymbolAddress((void**)&hb,   g_hb);
    cudaGetSymbolAddress((void**)&hb2,  g_hb2);
    cudaGetSymbolAddress((void**)&aob,  g_aob);
    cudaGetSymbolAddress((void**)&memb, g_memb);
    cudaGetSymbolAddress((void**)&ffnb, g_ffnb);
    cudaGetSymbolAddress((void**)&kvc,  g_kvc);
    cudaGetSymbolAddress((void**)&wp,   g_wpool);
    bf16* kc = kvc;
    bf16* vc = kvc + (size_t)NL * MD;

    cudaFuncSetAttribute(flash_kernel, cudaFuncAttributeMaxDynamicSharedMemorySize, FA_SMEM);
    cudaFuncSetAttribute((const void*)logsoftmax_kernel, cudaFuncAttributeMaxDynamicSharedMemorySize, LS_SMEM);

    const size_t DD = (size_t)D * D;
    dim3 fgrid(TT / 32, H, BBATCH);

    {
        void* args[] = {&enc_attn_w, &enc_ffn_w1, &enc_ffn_w2, &dec_attn_w,
                        &dec_ffn_w1, &dec_ffn_w2, &tok_emb, &wp};
        launch_pdl((const void*)cvt_all_kernel, dim3((C4_6 + 255) / 256), dim3(256), 0, args);
    }
    {
        const float *gA = enc_ln, *bA = enc_ln + D, *gB = dec_ln, *bB = dec_ln + D;
        void* args[] = {&src, &tgt, &tok_emb, &pos_emb, &gA, &bA, &gB, &bB,
                        &x, &x2, &hb, &hb2};
        launch_pdl((const void*)embed2_kernel, dim3(MROWS / 8, 2), dim3(256), 0, args);
    }

    // ================= encoder =================
    for (int i = 0; i < NL; i++) {
        const bf16*  W   = wp + OFF_EA + (size_t)i * 4 * DD;
        const float* Wb  = enc_attn_b + (size_t)i * 4 * D;
        const float* lnp = enc_ln + (size_t)i * 4 * D;

        G(hb, W, Wb, nullptr, qkv, MROWS, D, D, 0, 0, 1, 128, 3, 0, DD, D, MD);
        FL(fgrid, qkv, qkv + MD, qkv + 2 * MD, src, 0, aob);
        G(aob, W + 3 * DD, Wb + 3 * D, x, x, MROWS, D, D, 0, 0, 0, 64, 1, 0, 0, 0, 0);

        LN(x, lnp + 2 * D, lnp + 3 * D, hb);
        G2(0, dim3(FF / 128, MROWS / 128, 1),
           hb, wp + OFF_EF1 + (size_t)i * D * FF, enc_ffn_b1 + (size_t)i * FF,
           ffnb, MROWS, FF, D, 1, 0, 0, 0, 0, 0);
        G(ffnb, wp + OFF_EF2 + (size_t)i * FF * D, enc_ffn_b2 + (size_t)i * D,
          x, x, MROWS, D, FF, 0, 0, 0, 64, 1, 0, 0, 0, 0);
        if (i < NL - 1)
            LN(x, enc_ln + (size_t)(i + 1) * 4 * D, enc_ln + (size_t)(i + 1) * 4 * D + D, hb);
    }
    LN(x, enc_fln, enc_fln + D, memb);

    // cross-attention K/V for all decoder layers: single batch-12 launch
    G2(0, dim3(D / 128, MROWS / 128, 2 * NL),
       memb, wp + OFF_DA, dec_attn_b, kvc, MROWS, D, D, 0, 0, 0, 0, MD, 1);

    // ================= decoder =================
    for (int i = 0; i < NL; i++) {
        const bf16*  W   = wp + OFF_DA + (size_t)i * 8 * DD;
        const float* Wb  = dec_attn_b + (size_t)i * 8 * D;
        const float* lnp = dec_ln + (size_t)i * 6 * D;

        // self-attention
        G(hb2, W, Wb, nullptr, qkv, MROWS, D, D, 0, 0, 1, 128, 3, 0, DD, D, MD);
        FL(fgrid, qkv, qkv + MD, qkv + 2 * MD, tgt, 1, aob);
        G(aob, W + 3 * DD, Wb + 3 * D, x2, x2, MROWS, D, D, 0, 0, 0, 64, 1, 0, 0, 0, 0);

        // cross-attention
        LN(x2, lnp + 2 * D, lnp + 3 * D, hb2);
        G(hb2, W + 4 * DD, Wb + 4 * D, nullptr, qkv, MROWS, D, D, 0, 0, 1, 64, 1, 0, 0, 0, 0);
        FL(fgrid, qkv, kc + (size_t)i * MD, vc + (size_t)i * MD, src, 0, aob);
        G(aob, W + 7 * DD, Wb + 7 * D, x2, x2, MROWS, D, D, 0, 0, 0, 64, 1, 0, 0, 0, 0);

        // FFN
        LN(x2, lnp + 4 * D, lnp + 5 * D, hb2);
        G2(0, dim3(FF / 128, MROWS / 128, 1),
           hb2, wp + OFF_DF1 + (size_t)i * D * FF, dec_ffn_b1 + (size_t)i * FF,
           ffnb, MROWS, FF, D, 1, 0, 0, 0, 0, 0);
        G(ffnb, wp + OFF_DF2 + (size_t)i * FF * D, dec_ffn_b2 + (size_t)i * D,
          x2, x2, MROWS, D, FF, 0, 0, 0, 64, 1, 0, 0, 0, 0);
        if (i < NL - 1)
            LN(x2, dec_ln + (size_t)(i + 1) * 6 * D, dec_ln + (size_t)(i + 1) * 6 * D + D, hb2);
    }
    LN(x2, dec_fln, dec_fln + D, hb2);

    // ============ generator: tied projection + log_softmax ============
    G2(1, dim3(VV / 128, MROWS / 128, 1),
       hb2, wp + OFF_EMB, nullptr, out, MROWS, VV, D, 0, 0, 0, 0, 0, 0);
    {
        void* args[] = {&out};
        launch_pdl((const void*)logsoftmax_kernel, dim3(MROWS), dim3(512), LS_SMEM, args);
    }
}

// round 15
// speedup vs baseline: 1.0127x; 1.0127x over previous
#include <cuda_runtime.h>
#include <cuda_bf16.h>
#include <mma.h>
#include <cstddef>

using namespace nvcuda;
typedef __nv_bfloat16 bf16;

#define D    512
#define H    8
#define DK   64
#define TT   128
#define BBATCH 8
#define NL   6
#define VV   32000
#define FF   2048
#define MROWS (BBATCH*TT)
#define MD   (MROWS*D)

#define N_EA  (NL*4*D*D)
#define N_EF1 (NL*D*FF)
#define N_EF2 (NL*FF*D)
#define N_DA  (NL*8*D*D)
#define N_DF1 (NL*D*FF)
#define N_DF2 (NL*FF*D)
#define N_EMB (VV*D)
#define OFF_EA   0
#define OFF_EF1  (OFF_EA + N_EA)
#define OFF_EF2  (OFF_EF1 + N_EF1)
#define OFF_DA   (OFF_EF2 + N_EF2)
#define OFF_DF1  (OFF_DA + N_DA)
#define OFF_DF2  (OFF_DF1 + N_DF1)
#define OFF_EMB  (OFF_DF2 + N_DF2)
#define WPOOL_N  (OFF_EMB + N_EMB)

__device__ float g_x  [MD];
__device__ float g_x2 [MD];
__device__ bf16  g_qkv[3*MD];
__device__ bf16  g_hb [MD];
__device__ bf16  g_hb2[MD];
__device__ bf16  g_aob[MD];
__device__ bf16  g_memb[MD];
__device__ bf16  g_ffnb[MROWS*FF];
__device__ bf16  g_kvc[2*NL*MD];
__device__ bf16  g_wpool[WPOOL_N];

// ---------------- PDL ----------------
__device__ __forceinline__ void gdc_wait() {
    asm volatile("griddepcontrol.wait;" ::: "memory");
}

// ---------------- cp.async helpers ----------------
__device__ __forceinline__ void cpa16(void* dst, const void* src) {
    unsigned sdst = (unsigned)__cvta_generic_to_shared(dst);
    asm volatile("cp.async.cg.shared.global [%0], [%1], 16;\n" :: "r"(sdst), "l"(src));
}
__device__ __forceinline__ void cpa_commit() { asm volatile("cp.async.commit_group;\n"); }
template<int N>
__device__ __forceinline__ void cpa_wait() { asm volatile("cp.async.wait_group %0;\n" :: "n"(N)); }

// ---------------- merged fp32 -> bf16 conversion ----------------
#define C4_0 (N_EA/4)
#define C4_1 (C4_0 + N_EF1/4)
#define C4_2 (C4_1 + N_EF2/4)
#define C4_3 (C4_2 + N_DA/4)
#define C4_4 (C4_3 + N_DF1/4)
#define C4_5 (C4_4 + N_DF2/4)
#define C4_6 (C4_5 + N_EMB/4)

__global__ void cvt_all_kernel(const float* __restrict__ s0, const float* __restrict__ s1,
                               const float* __restrict__ s2, const float* __restrict__ s3,
                               const float* __restrict__ s4, const float* __restrict__ s5,
                               const float* __restrict__ s6, bf16* __restrict__ pool) {
    gdc_wait();
    int i = blockIdx.x * blockDim.x + threadIdx.x;
    if (i >= C4_6) return;
    const float* s;
    int off;
    if      (i < C4_0) { s = s0; off = i; }
    else if (i < C4_1) { s = s1; off = i - C4_0; }
    else if (i < C4_2) { s = s2; off = i - C4_1; }
    else if (i < C4_3) { s = s3; off = i - C4_2; }
    else if (i < C4_4) { s = s4; off = i - C4_3; }
    else if (i < C4_5) { s = s5; off = i - C4_4; }
    else               { s = s6; off = i - C4_5; }
    float4 v = reinterpret_cast<const float4*>(s)[off];
    __nv_bfloat162* o = reinterpret_cast<__nv_bfloat162*>(pool) + 2 * (size_t)i;
    o[0] = __floats2bfloat162_rn(v.x, v.y);
    o[1] = __floats2bfloat162_rn(v.z, v.w);
}

// ---------------- embedding + LN fused, both stacks in one launch ----------------
__global__ __launch_bounds__(256) void embed2_kernel(
        const int* __restrict__ tokA, const int* __restrict__ tokB,
        const float* __restrict__ tok_emb, const float* __restrict__ pos_emb,
        const float* __restrict__ gA, const float* __restrict__ bA,
        const float* __restrict__ gB, const float* __restrict__ bB,
        float* __restrict__ xA, float* __restrict__ xB,
        bf16* __restrict__ hA, bf16* __restrict__ hB) {
    gdc_wait();
    int set = blockIdx.y;
    const int*   tok = set ? tokB : tokA;
    const float* g   = set ? gB : gA;
    const float* b   = set ? bB : bA;
    float*       xo  = set ? xB : xA;
    bf16*        ho  = set ? hB : hA;

    int row  = blockIdx.x * 8 + (threadIdx.x >> 5);
    int lane = threadIdx.x & 31;
    int t = row % TT;
    const float4* te = reinterpret_cast<const float4*>(tok_emb + (size_t)tok[row] * D);
    const float4* pe = reinterpret_cast<const float4*>(pos_emb + (size_t)t * D);
    float4* x4 = reinterpret_cast<float4*>(xo + (size_t)row * D);

    float4 v[4];
    float s = 0.f;
    #pragma unroll
    for (int j = 0; j < 4; j++) {
        int c = lane + j * 32;
        float4 a = te[c], p = pe[c];
        v[j].x = a.x + p.x; v[j].y = a.y + p.y; v[j].z = a.z + p.z; v[j].w = a.w + p.w;
        x4[c] = v[j];
        s += v[j].x + v[j].y + v[j].z + v[j].w;
    }
    #pragma unroll
    for (int o = 16; o; o >>= 1) s += __shfl_xor_sync(0xffffffffu, s, o);
    float mu = s * (1.f / D);

    float var = 0.f;
    #pragma unroll
    for (int j = 0; j < 4; j++) {
        float a0 = v[j].x - mu, a1 = v[j].y - mu, a2 = v[j].z - mu, a3 = v[j].w - mu;
        var += a0 * a0 + a1 * a1 + a2 * a2 + a3 * a3;
    }
    #pragma unroll
    for (int o = 16; o; o >>= 1) var += __shfl_xor_sync(0xffffffffu, var, o);
    float inv = rsqrtf(var * (1.f / D) + 1e-6f);

    const float4* g4 = reinterpret_cast<const float4*>(g);
    const float4* b4 = reinterpret_cast<const float4*>(b);
    uint2* o8 = reinterpret_cast<uint2*>(ho + (size_t)row * D);
    #pragma unroll
    for (int j = 0; j < 4; j++) {
        int c = lane + j * 32;
        float4 gg = g4[c], bb = b4[c];
        float r0 = (v[j].x - mu) * inv * gg.x + bb.x;
        float r1 = (v[j].y - mu) * inv * gg.y + bb.y;
        float r2 = (v[j].z - mu) * inv * gg.z + bb.z;
        float r3 = (v[j].w - mu) * inv * gg.w + bb.w;
        __nv_bfloat162 lo = __floats2bfloat162_rn(r0, r1);
        __nv_bfloat162 hi = __floats2bfloat162_rn(r2, r3);
        uint2 pk; pk.x = *reinterpret_cast<unsigned*>(&lo); pk.y = *reinterpret_cast<unsigned*>(&hi);
        o8[c] = pk;
    }
}

// ---------------- layernorm: warp per row, 8 rows/block ----------------
__global__ __launch_bounds__(256) void ln_kernel(const float* __restrict__ x,
                          const float* __restrict__ g,
                          const float* __restrict__ b,
                          bf16* __restrict__ out) {
    gdc_wait();
    int row  = blockIdx.x * 8 + (threadIdx.x >> 5);
    int lane = threadIdx.x & 31;
    const float4* xr = reinterpret_cast<const float4*>(x + (size_t)row * D);

    float4 v[4];
    float s = 0.f;
    #pragma unroll
    for (int j = 0; j < 4; j++) {
        v[j] = xr[lane + j * 32];
        s += v[j].x + v[j].y + v[j].z + v[j].w;
    }
    #pragma unroll
    for (int o = 16; o; o >>= 1) s += __shfl_xor_sync(0xffffffffu, s, o);
    float mu = s * (1.f / D);

    float var = 0.f;
    #pragma unroll
    for (int j = 0; j < 4; j++) {
        float a0 = v[j].x - mu, a1 = v[j].y - mu, a2 = v[j].z - mu, a3 = v[j].w - mu;
        var += a0 * a0 + a1 * a1 + a2 * a2 + a3 * a3;
    }
    #pragma unroll
    for (int o = 16; o; o >>= 1) var += __shfl_xor_sync(0xffffffffu, var, o);
    float inv = rsqrtf(var * (1.f / D) + 1e-6f);

    const float4* g4 = reinterpret_cast<const float4*>(g);
    const float4* b4 = reinterpret_cast<const float4*>(b);
    uint2* o8 = reinterpret_cast<uint2*>(out + (size_t)row * D);
    #pragma unroll
    for (int j = 0; j < 4; j++) {
        int c = lane + j * 32;
        float4 gg = g4[c], bb = b4[c];
        float r0 = (v[j].x - mu) * inv * gg.x + bb.x;
        float r1 = (v[j].y - mu) * inv * gg.y + bb.y;
        float r2 = (v[j].z - mu) * inv * gg.z + bb.z;
        float r3 = (v[j].w - mu) * inv * gg.w + bb.w;
        __nv_bfloat162 lo = __floats2bfloat162_rn(r0, r1);
        __nv_bfloat162 hi = __floats2bfloat162_rn(r2, r3);
        uint2 pk; pk.x = *reinterpret_cast<unsigned*>(&lo); pk.y = *reinterpret_cast<unsigned*>(&hi);
        o8[c] = pk;
    }
}

// ---------------- bf16 GEMM, 2-stage cp.async BK=32 (R13 proven) ----------------
#define ASTR 48
#define BSTR0 72
#define BSTR1 48
#define BSZ (64*BSTR1)

template<int TB, int OB, int MT>
__global__ __launch_bounds__(256) void wgemm(
        const bf16* __restrict__ Ag, const bf16* __restrict__ Bg,
        const float* __restrict__ bias, const float* __restrict__ res,
        void* __restrict__ Cv, int M, int N, int K, int relu,
        size_t sA, size_t sB, size_t sBias, size_t sC) {
    gdc_wait();
    constexpr int WSM = MT / 32;
    constexpr int WSN = 8 / WSM;
    constexpr int NFR = 64 / (WSN * 16);
    constexpr int ASZ = MT * ASTR;

    const int z = blockIdx.z;
    const bf16* A = Ag + (size_t)z * sA;
    const bf16* B = Bg + (size_t)z * sB;
    const float* bi = bias ? bias + (size_t)z * sBias : nullptr;

    __shared__ __align__(16) char smem_raw[36864];
    bf16*  Abase = reinterpret_cast<bf16*>(smem_raw);
    bf16*  Bbase = Abase + 2 * ASZ;
    float* Cs    = reinterpret_cast<float*>(smem_raw);

    const int tid  = threadIdx.x;
    const int warp = tid >> 5;
    const int wm   = warp % WSM;
    const int wn   = warp / WSM;
    const int wnoff = wn * 16 * NFR;
    const int m0 = blockIdx.y * MT, n0 = blockIdx.x * 64;

    wmma::fragment<wmma::accumulator, 16, 16, 16, float> acc[2][NFR];
    #pragma unroll
    for (int i = 0; i < 2; i++)
        #pragma unroll
        for (int j = 0; j < NFR; j++) wmma::fill_fragment(acc[i][j], 0.f);

    auto load_stage = [&](int s, int k0) {
        bf16* As = Abase + s * ASZ;
        bf16* Bs = Bbase + s * BSZ;
        #pragma unroll
        for (int it = 0; it < MT / 64; it++) {
            int chunk = tid + it * 256;
            int r = chunk >> 2, c = (chunk & 3) << 3;
            cpa16(&As[r * ASTR + c], &A[(size_t)(m0 + r) * K + k0 + c]);
        }
        if (TB == 0) {
            int r = tid >> 3, c = (tid & 7) << 3;
            cpa16(&Bs[r * BSTR0 + c], &B[(size_t)(k0 + r) * N + n0 + c]);
        } else {
            int r = tid >> 2, c = (tid & 3) << 3;
            cpa16(&Bs[r * BSTR1 + c], &B[(size_t)(n0 + r) * K + k0 + c]);
        }
    };

    auto compute_stage = [&](int s) {
        bf16* As = Abase + s * ASZ;
        bf16* Bs = Bbase + s * BSZ;
        #pragma unroll
        for (int kk = 0; kk < 32; kk += 16) {
            wmma::fragment<wmma::matrix_a, 16, 16, 16, bf16, wmma::row_major> a0, a1;
            wmma::load_matrix_sync(a0, &As[(wm * 32 +  0) * ASTR + kk], ASTR);
            wmma::load_matrix_sync(a1, &As[(wm * 32 + 16) * ASTR + kk], ASTR);
            #pragma unroll
            for (int j = 0; j < NFR; j++) {
                if (TB == 0) {
                    wmma::fragment<wmma::matrix_b, 16, 16, 16, bf16, wmma::row_major> bf;
                    wmma::load_matrix_sync(bf, &Bs[kk * BSTR0 + wnoff + j * 16], BSTR0);
                    wmma::mma_sync(acc[0][j], a0, bf, acc[0][j]);
                    wmma::mma_sync(acc[1][j], a1, bf, acc[1][j]);
                } else {
                    wmma::fragment<wmma::matrix_b, 16, 16, 16, bf16, wmma::col_major> bf;
                    wmma::load_matrix_sync(bf, &Bs[(wnoff + j * 16) * BSTR1 + kk], BSTR1);
                    wmma::mma_sync(acc[0][j], a0, bf, acc[0][j]);
                    wmma::mma_sync(acc[1][j], a1, bf, acc[1][j]);
                }
            }
        }
    };

    const int KT = K >> 5;
    load_stage(0, 0);
    cpa_commit();
    for (int kt = 0; kt < KT; kt++) {
        if (kt + 1 < KT) { load_stage((kt + 1) & 1, (kt + 1) << 5); cpa_commit(); cpa_wait<1>(); }
        else             { cpa_wait<0>(); }
        __syncthreads();
        compute_stage(kt & 1);
        __syncthreads();
    }

    #pragma unroll
    for (int i = 0; i < 2; i++)
        #pragma unroll
        for (int j = 0; j < NFR; j++)
            wmma::store_matrix_sync(&Cs[(wm * 32 + i * 16) * 72 + wnoff + j * 16],
                                    acc[i][j], 72, wmma::mem_row_major);
    __syncthreads();

    #pragma unroll
    for (int it = 0; it < MT / 4; it++) {
        int idx = tid + it * 256;
        int r = idx >> 6, c = idx & 63;
        int m = m0 + r, n = n0 + c;
        float val = Cs[r * 72 + c];
        if (bi)   val += bi[n];
        if (relu) val = fmaxf(val, 0.f);
        if (OB) {
            reinterpret_cast<bf16*>(Cv)[(size_t)z * sC + (size_t)m * N + n] = __float2bfloat16(val);
        } else {
            float* C = reinterpret_cast<float*>(Cv) + (size_t)z * sC;
            if (res) val += res[(size_t)m * N + n];
            C[(size_t)m * N + n] = val;
        }
    }
}

// ---------------- 32x64-tile bf16 GEMM: >1-wave grids for skinny-N launches ----------------
// 8 warps as 2(M) x 4(N), one 16x16 acc each; TB=0 only.
template<int OB>
__global__ __launch_bounds__(256) void wgemm32(
        const bf16* __restrict__ A, const bf16* __restrict__ B,
        const float* __restrict__ bias, const float* __restrict__ res,
        void* __restrict__ Cv, int M, int N, int K, int relu) {
    gdc_wait();
    constexpr int A3SZ = 32 * ASTR;      // 1536
    __shared__ __align__(16) char smem_raw[(2 * (A3SZ + 32 * BSTR0)) * 2];
    bf16*  Abase = reinterpret_cast<bf16*>(smem_raw);
    bf16*  Bbase = Abase + 2 * A3SZ;
    float* Cs    = reinterpret_cast<float*>(smem_raw);   // 32x72 fp32 = 9216B, fits

    const int tid  = threadIdx.x;
    const int warp = tid >> 5;
    const int wm   = warp & 1;       // 0..1 (16-row units)
    const int wn   = warp >> 1;      // 0..3 (16-col units)
    const int m0 = blockIdx.y * 32, n0 = blockIdx.x * 64;

    wmma::fragment<wmma::accumulator, 16, 16, 16, float> acc;
    wmma::fill_fragment(acc, 0.f);

    auto load_stage = [&](int s, int k0) {
        bf16* As = Abase + s * A3SZ;
        bf16* Bs = Bbase + s * (32 * BSTR0);
        if (tid < 128) {                       // A: 32x32, 128 chunks
            int r = tid >> 2, c = (tid & 3) << 3;
            cpa16(&As[r * ASTR + c], &A[(size_t)(m0 + r) * K + k0 + c]);
        }
        {                                      // B: 32x64, 256 chunks
            int r = tid >> 3, c = (tid & 7) << 3;
            cpa16(&Bs[r * BSTR0 + c], &B[(size_t)(k0 + r) * N + n0 + c]);
        }
    };

    auto compute_stage = [&](int s) {
        bf16* As = Abase + s * A3SZ;
        bf16* Bs = Bbase + s * (32 * BSTR0);
        #pragma unroll
        for (int kk = 0; kk < 32; kk += 16) {
            wmma::fragment<wmma::matrix_a, 16, 16, 16, bf16, wmma::row_major> a;
            wmma::fragment<wmma::matrix_b, 16, 16, 16, bf16, wmma::row_major> bf;
            wmma::load_matrix_sync(a, &As[(wm * 16) * ASTR + kk], ASTR);
            wmma::load_matrix_sync(bf, &Bs[kk * BSTR0 + wn * 16], BSTR0);
            wmma::mma_sync(acc, a, bf, acc);
        }
    };

    const int KT = K >> 5;
    load_stage(0, 0);
    cpa_commit();
    for (int kt = 0; kt < KT; kt++) {
        if (kt + 1 < KT) { load_stage((kt + 1) & 1, (kt + 1) << 5); cpa_commit(); cpa_wait<1>(); }
        else             { cpa_wait<0>(); }
        __syncthreads();
        compute_stage(kt & 1);
        __syncthreads();
    }

    wmma::store_matrix_sync(&Cs[(wm * 16) * 72 + wn * 16], acc, 72, wmma::mem_row_major);
    __syncthreads();

    #pragma unroll
    for (int it = 0; it < 8; it++) {
        int idx = tid + it * 256;                // 32*64 = 2048
        int r = idx >> 6, c = idx & 63;
        int m = m0 + r, n = n0 + c;
        float val = Cs[r * 72 + c];
        if (bias) val += bias[n];
        if (relu) val = fmaxf(val, 0.f);
        if (OB) {
            reinterpret_cast<bf16*>(Cv)[(size_t)m * N + n] = __float2bfloat16(val);
        } else {
            float* C = reinterpret_cast<float*>(Cv);
            if (res) val += res[(size_t)m * N + n];
            C[(size_t)m * N + n] = val;
        }
    }
}

// ---------------- 128x128 bf16 GEMM (BK=32, static smem; kvmode) ----------------
#define A2STR 40
#define B2STR0 136
#define B2STR1 40

template<int TB, int EPI>
__global__ __launch_bounds__(256) void wgemm2(
        const bf16* __restrict__ Ag, const bf16* __restrict__ Bg,
        const float* __restrict__ bias, void* __restrict__ Cv,
        int M, int N, int K, int relu,
        size_t sA, size_t sB, size_t sBias, size_t sC, int kvmode) {
    gdc_wait();
    constexpr int BST   = TB ? B2STR1 : B2STR0;
    constexpr int BROWS = TB ? 128 : 32;
    constexpr int A2SZ  = 128 * A2STR;
    constexpr int B2SZ  = BROWS * BST;
    constexpr int STG2  = A2SZ + B2SZ;

    const int z = blockIdx.z;
    size_t zA, zB, zBias, zC;
    if (kvmode) {
        int layer = z >> 1, kv = z & 1;
        zA = 0;
        zB = ((size_t)layer * 8 + 5 + kv) * (size_t)D * D;
        zBias = ((size_t)layer * 8 + 5 + kv) * D;
        zC = (size_t)(kv * NL + layer) * sC;
    } else {
        zA = (size_t)z * sA; zB = (size_t)z * sB;
        zBias = (size_t)z * sBias; zC = (size_t)z * sC;
    }
    const bf16* A = Ag + zA;
    const bf16* B = Bg + zB;
    const float* bi = bias ? bias + zBias : nullptr;

    __shared__ __align__(16) bf16 sm[2 * STG2];
    float* Cs = reinterpret_cast<float*>(sm);

    const int tid  = threadIdx.x;
    const int warp = tid >> 5;
    const int wm   = warp & 3;
    const int wn   = warp >> 2;
    const int m0 = blockIdx.y * 128, n0 = blockIdx.x * 128;

    wmma::fragment<wmma::accumulator, 16, 16, 16, float> acc[2][4];
    #pragma unroll
    for (int i = 0; i < 2; i++)
        #pragma unroll
        for (int j = 0; j < 4; j++) wmma::fill_fragment(acc[i][j], 0.f);

    auto load_stage = [&](int s, int k0) {
        bf16* As = sm + s * STG2;
        bf16* Bs = As + A2SZ;
        #pragma unroll
        for (int it = 0; it < 2; it++) {
            int chunk = tid + it * 256;
            int r = chunk >> 2, c = (chunk & 3) << 3;
            cpa16(&As[r * A2STR + c], &A[(size_t)(m0 + r) * K + k0 + c]);
        }
        if (TB == 0) {
            #pragma unroll
            for (int it = 0; it < 2; it++) {
                int chunk = tid + it * 256;
                int r = chunk >> 4, c = (chunk & 15) << 3;
                cpa16(&Bs[r * B2STR0 + c], &B[(size_t)(k0 + r) * N + n0 + c]);
            }
        } else {
            #pragma unroll
            for (int it = 0; it < 2; it++) {
                int chunk = tid + it * 256;
                int r = chunk >> 2, c = (chunk & 3) << 3;
                cpa16(&Bs[r * B2STR1 + c], &B[(size_t)(n0 + r) * K + k0 + c]);
            }
        }
    };

    auto compute_stage = [&](int s) {
        bf16* As = sm + s * STG2;
        bf16* Bs = As + A2SZ;
        #pragma unroll
        for (int kk = 0; kk < 32; kk += 16) {
            wmma::fragment<wmma::matrix_a, 16, 16, 16, bf16, wmma::row_major> a0, a1;
            wmma::load_matrix_sync(a0, &As[(wm * 32 +  0) * A2STR + kk], A2STR);
            wmma::load_matrix_sync(a1, &As[(wm * 32 + 16) * A2STR + kk], A2STR);
            #pragma unroll
            for (int j = 0; j < 4; j++) {
                if (TB == 0) {
                    wmma::fragment<wmma::matrix_b, 16, 16, 16, bf16, wmma::row_major> bf;
                    wmma::load_matrix_sync(bf, &Bs[kk * B2STR0 + wn * 64 + j * 16], B2STR0);
                    wmma::mma_sync(acc[0][j], a0, bf, acc[0][j]);
                    wmma::mma_sync(acc[1][j], a1, bf, acc[1][j]);
                } else {
                    wmma::fragment<wmma::matrix_b, 16, 16, 16, bf16, wmma::col_major> bf;
                    wmma::load_matrix_sync(bf, &Bs[(wn * 64 + j * 16) * B2STR1 + kk], B2STR1);
                    wmma::mma_sync(acc[0][j], a0, bf, acc[0][j]);
                    wmma::mma_sync(acc[1][j], a1, bf, acc[1][j]);
                }
            }
        }
    };

    const int KT = K >> 5;
    load_stage(0, 0);
    cpa_commit();
    for (int kt = 0; kt < KT; kt++) {
        if (kt + 1 < KT) { load_stage((kt + 1) & 1, (kt + 1) << 5); cpa_commit(); cpa_wait<1>(); }
        else             { cpa_wait<0>(); }
        __syncthreads();
        compute_stage(kt & 1);
        __syncthreads();
    }

    if (EPI == 0) {
        float* C = reinterpret_cast<float*>(Cv) + zC;
        #pragma unroll
        for (int i = 0; i < 2; i++)
            #pragma unroll
            for (int j = 0; j < 4; j++)
                wmma::store_matrix_sync(
                    &C[(size_t)(m0 + wm * 32 + i * 16) * N + n0 + wn * 64 + j * 16],
                    acc[i][j], N, wmma::mem_row_major);
    } else {
        bf16* Co = reinterpret_cast<bf16*>(Cv) + zC;
        #pragma unroll
        for (int hh = 0; hh < 2; hh++) {
            if ((wm >> 1) == hh) {
                #pragma unroll
                for (int i = 0; i < 2; i++)
                    #pragma unroll
                    for (int j = 0; j < 4; j++)
                        wmma::store_matrix_sync(
                            &Cs[((wm & 1) * 32 + i * 16) * 136 + wn * 64 + j * 16],
                            acc[i][j], 136, wmma::mem_row_major);
            }
            __syncthreads();
            #pragma unroll
            for (int it = 0; it < 32; it++) {
                int idx = tid + it * 256;
                int r = idx >> 7, c = idx & 127;
                int m = m0 + hh * 64 + r, n = n0 + c;
                float val = Cs[r * 136 + c];
                if (bi)   val += bi[n];
                if (relu) val = fmaxf(val, 0.f);
                Co[(size_t)m * N + n] = __float2bfloat16(val);
            }
            __syncthreads();
        }
    }
}

// ---------------- fused flash attention: Q-tile 32, async K/V loads ----------------
#define FA_SMEM 58368

__global__ __launch_bounds__(256) void flash_kernel(
        const bf16* __restrict__ Q, const bf16* __restrict__ Kp, const bf16* __restrict__ Vp,
        const int* __restrict__ toks, int causal, bf16* __restrict__ out) {
    gdc_wait();
    extern __shared__ __align__(16) char sm[];
    bf16*  Qs = reinterpret_cast<bf16*>(sm);
    bf16*  Ks = Qs + 32 * 72;
    bf16*  Vs = Ks + 128 * 72;
    float* S  = reinterpret_cast<float*>(sm + 41472);
    bf16*  Pb = reinterpret_cast<bf16*>(sm);
    __shared__ int msk[TT];

    const int q0 = blockIdx.x * 32;
    const int h  = blockIdx.y;
    const int b  = blockIdx.z;
    const int tid = threadIdx.x, warp = tid >> 5, lane = tid & 31;

    #pragma unroll
    for (int it = 0; it < 4; it++) {
        int ch = tid + it * 256;
        int r = ch >> 3, c = (ch & 7) << 3;
        cpa16(&Ks[r * 72 + c], &Kp[(size_t)(b * TT + r) * D + h * DK + c]);
    }
    cpa_commit();
    #pragma unroll
    for (int it = 0; it < 4; it++) {
        int ch = tid + it * 256;
        int r = ch >> 3, c = (ch & 7) << 3;
        cpa16(&Vs[r * 72 + c], &Vp[(size_t)(b * TT + r) * D + h * DK + c]);
    }
    cpa_commit();
    {
        int r = tid >> 3, c = (tid & 7) << 3;
        *reinterpret_cast<uint4*>(&Qs[r * 72 + c]) =
            *reinterpret_cast<const uint4*>(&Q[(size_t)(b * TT + q0 + r) * D + h * DK + c]);
    }
    if (tid < TT) msk[tid] = (toks[b * TT + tid] == 1);
    cpa_wait<1>();
    __syncthreads();

    {
        int wm = warp & 1, wn = warp >> 1;
        #pragma unroll
        for (int n = 0; n < 2; n++) {
            wmma::fragment<wmma::accumulator, 16, 16, 16, float> acc;
            wmma::fill_fragment(acc, 0.f);
            #pragma unroll
            for (int kk = 0; kk < 4; kk++) {
                wmma::fragment<wmma::matrix_a, 16, 16, 16, bf16, wmma::row_major> a;
                wmma::fragment<wmma::matrix_b, 16, 16, 16, bf16, wmma::col_major> bb;
                wmma::load_matrix_sync(a, &Qs[(wm * 16) * 72 + kk * 16], 72);
                wmma::load_matrix_sync(bb, &Ks[(wn * 32 + n * 16) * 72 + kk * 16], 72);
                wmma::mma_sync(acc, a, bb, acc);
            }
            wmma::store_matrix_sync(&S[(wm * 16) * 132 + wn * 32 + n * 16], acc, 132,
                                    wmma::mem_row_major);
        }
    }
    __syncthreads();

    for (int rr = 0; rr < 4; rr++) {
        int r = warp * 4 + rr;
        int qg = q0 + r;
        float v[4];
        #pragma unroll
        for (int j = 0; j < 4; j++) {
            int col = lane + j * 32;
            float s = S[r * 132 + col] * 0.125f;
            if (msk[col] || (causal && col > qg)) s = -1e30f;
            v[j] = s;
        }
        float m = fmaxf(fmaxf(v[0], v[1]), fmaxf(v[2], v[3]));
        #pragma unroll
        for (int o = 16; o; o >>= 1) m = fmaxf(m, __shfl_xor_sync(0xffffffffu, m, o));
        float e[4], sum = 0.f;
        #pragma unroll
        for (int j = 0; j < 4; j++) { e[j] = __expf(v[j] - m); sum += e[j]; }
        #pragma unroll
        for (int o = 16; o; o >>= 1) sum += __shfl_xor_sync(0xffffffffu, sum, o);
        float inv = __frcp_rn(sum);
        #pragma unroll
        for (int j = 0; j < 4; j++)
            Pb[r * 136 + lane + j * 32] = __float2bfloat16(e[j] * inv);
    }
    cpa_wait<0>();
    __syncthreads();

    {
        int wm = warp & 1, wn = warp >> 1;
        wmma::fragment<wmma::accumulator, 16, 16, 16, float> acc;
        wmma::fill_fragment(acc, 0.f);
        #pragma unroll
        for (int kk = 0; kk < 8; kk++) {
            wmma::fragment<wmma::matrix_a, 16, 16, 16, bf16, wmma::row_major> a;
            wmma::fragment<wmma::matrix_b, 16, 16, 16, bf16, wmma::row_major> bb;
            wmma::load_matrix_sync(a, &Pb[(wm * 16) * 136 + kk * 16], 136);
            wmma::load_matrix_sync(bb, &Vs[(kk * 16) * 72 + wn * 16], 72);
            wmma::mma_sync(acc, a, bb, acc);
        }
        wmma::store_matrix_sync(&S[(wm * 16) * 132 + wn * 16], acc, 132,
                                wmma::mem_row_major);
    }
    __syncthreads();

    for (int idx = tid; idx < 32 * 64; idx += 256) {
        int r = idx >> 6, c = idx & 63;
        out[(size_t)(b * TT + q0 + r) * D + h * DK + c] = __float2bfloat16(S[r * 132 + c]);
    }
}

// ---------------- log_softmax: row cached in dynamic smem ----------------
#define LS_SMEM (VV*4)

__global__ __launch_bounds__(512) void logsoftmax_kernel(float* __restrict__ logits) {
    gdc_wait();
    extern __shared__ float xs[];
    int row = blockIdx.x;
    float* x = logits + (size_t)row * VV;
    __shared__ float shm[512], shs[512];
    int tid = threadIdx.x;

    float m = -1e30f, s = 0.f;
    for (int i = tid; i < VV / 4; i += 512) {
        float4 v = reinterpret_cast<const float4*>(x)[i];
        reinterpret_cast<float4*>(xs)[i] = v;
        float cm = fmaxf(fmaxf(v.x, v.y), fmaxf(v.z, v.w));
        if (cm > m) { s *= __expf(m - cm); m = cm; }
        s += __expf(v.x - m) + __expf(v.y - m) + __expf(v.z - m) + __expf(v.w - m);
    }
    shm[tid] = m; shs[tid] = s; __syncthreads();
    for (int o = 256; o; o >>= 1) {
        if (tid < o) {
            float m2 = shm[tid + o], s2 = shs[tid + o];
            float mn = fmaxf(shm[tid], m2);
            shs[tid] = shs[tid] * __expf(shm[tid] - mn) + s2 * __expf(m2 - mn);
            shm[tid] = mn;
        }
        __syncthreads();
    }
    float lse = shm[0] + logf(shs[0]);

    for (int i = tid; i < VV / 4; i += 512) {
        float4 v = reinterpret_cast<float4*>(xs)[i];
        v.x -= lse; v.y -= lse; v.z -= lse; v.w -= lse;
        reinterpret_cast<float4*>(x)[i] = v;
    }
}

// ---------------- host: PDL launch helper ----------------
static void launch_pdl(const void* func, dim3 grid, dim3 block, size_t smem, void** args) {
    cudaLaunchAttribute attr;
    attr.id = cudaLaunchAttributeProgrammaticStreamSerialization;
    attr.val.programmaticStreamSerializationAllowed = 1;
    cudaLaunchConfig_t cfg = {};
    cfg.gridDim = grid;
    cfg.blockDim = block;
    cfg.dynamicSmemBytes = smem;
    cfg.stream = 0;
    cfg.attrs = &attr;
    cfg.numAttrs = 1;
    cudaLaunchKernelExC(&cfg, func, args);
}

static void G(const bf16* A, const bf16* B, const float* bias, const float* res,
              void* C, int M, int N, int K, int relu, int tb, int ob, int mt, int batch,
              size_t sA, size_t sB, size_t sBias, size_t sC) {
    dim3 grid(N / 64, M / mt, batch);
    void* args[] = {&A, &B, &bias, &res, &C, &M, &N, &K, &relu, &sA, &sB, &sBias, &sC};
    const void* f;
    if (tb)                    f = (const void*)wgemm<1, 0, 128>;
    else if (ob && mt == 128)  f = (const void*)wgemm<0, 1, 128>;
    else if (ob)               f = (const void*)wgemm<0, 1, 64>;
    else                       f = (const void*)wgemm<0, 0, 64>;
    launch_pdl(f, grid, dim3(256), 0, args);
}

// 32x64-tile GEMM for skinny-N single launches (>1 wave)
static void G32(const bf16* A, const bf16* B, const float* bias, const float* res,
                void* C, int M, int N, int K, int relu, int ob) {
    dim3 grid(N / 64, M / 32);
    void* args[] = {&A, &B, &bias, &res, &C, &M, &N, &K, &relu};
    const void* f = ob ? (const void*)wgemm32<1> : (const void*)wgemm32<0>;
    launch_pdl(f, grid, dim3(256), 0, args);
}

static void G2(int variant, dim3 grid, const bf16* A, const bf16* B, const float* bias,
               void* C, int M, int N, int K, int relu,
               size_t sA, size_t sB, size_t sBias, size_t sC, int kvmode) {
    void* args[] = {&A, &B, &bias, &C, &M, &N, &K, &relu, &sA, &sB, &sBias, &sC, &kvmode};
    const void* f = variant ? (const void*)wgemm2<1, 0> : (const void*)wgemm2<0, 1>;
    launch_pdl(f, grid, dim3(256), 0, args);
}

static void FL(dim3 grid, const bf16* Q, const bf16* Kp, const bf16* Vp,
               const int* toks, int causal, bf16* out) {
    void* args[] = {&Q, &Kp, &Vp, &toks, &causal, &out};
    launch_pdl((const void*)flash_kernel, grid, dim3(256), FA_SMEM, args);
}

static void LN(const float* x, const float* g, const float* b, bf16* out) {
    void* args[] = {&x, &g, &b, &out};
    launch_pdl((const void*)ln_kernel, dim3(MROWS / 8), dim3(256), 0, args);
}

extern "C" void kernel_launch(void* const* d_in, const int* in_sizes, int n_in,
                              void* d_out, int out_size) {
    const int*   src        = (const int*)  d_in[0];
    const int*   tgt        = (const int*)  d_in[1];
    const float* tok_emb    = (const float*)d_in[2];
    const float* pos_emb    = (const float*)d_in[3];
    const float* enc_attn_w = (const float*)d_in[4];
    const float* enc_attn_b = (const float*)d_in[5];
    const float* enc_ffn_w1 = (const float*)d_in[6];
    const float* enc_ffn_b1 = (const float*)d_in[7];
    const float* enc_ffn_w2 = (const float*)d_in[8];
    const float* enc_ffn_b2 = (const float*)d_in[9];
    const float* enc_ln     = (const float*)d_in[10];
    const float* enc_fln    = (const float*)d_in[11];
    const float* dec_attn_w = (const float*)d_in[12];
    const float* dec_attn_b = (const float*)d_in[13];
    const float* dec_ffn_w1 = (const float*)d_in[14];
    const float* dec_ffn_b1 = (const float*)d_in[15];
    const float* dec_ffn_w2 = (const float*)d_in[16];
    const float* dec_ffn_b2 = (const float*)d_in[17];
    const float* dec_ln     = (const float*)d_in[18];
    const float* dec_fln    = (const float*)d_in[19];
    float* out = (float*)d_out;

    float *x, *x2;
    bf16 *qkv, *hb, *hb2, *aob, *memb, *ffnb, *kvc, *wp;
    cudaGetSymbolAddress((void**)&x,    g_x);
    cudaGetSymbolAddress((void**)&x2,   g_x2);
    cudaGetSymbolAddress((void**)&qkv,  g_qkv);
    cudaGetSymbolAddress((void**)&hb,   g_hb);
    cudaGetSymbolAddress((void**)&hb2,  g_hb2);
    cudaGetSymbolAddress((void**)&aob,  g_aob);
    cudaGetSymbolAddress((void**)&memb, g_memb);
    cudaGetSymbolAddress((void**)&ffnb, g_ffnb);
    cudaGetSymbolAddress((void**)&kvc,  g_kvc);
    cudaGetSymbolAddress((void**)&wp,   g_wpool);
    bf16* kc = kvc;
    bf16* vc = kvc + (size_t)NL * MD;

    cudaFuncSetAttribute(flash_kernel, cudaFuncAttributeMaxDynamicSharedMemorySize, FA_SMEM);
    cudaFuncSetAttribute((const void*)logsoftmax_kernel, cudaFuncAttributeMaxDynamicSharedMemorySize, LS_SMEM);

    const size_t DD = (size_t)D * D;
    dim3 fgrid(TT / 32, H, BBATCH);

    {
        void* args[] = {&enc_attn_w, &enc_ffn_w1, &enc_ffn_w2, &dec_attn_w,
                        &dec_ffn_w1, &dec_ffn_w2, &tok_emb, &wp};
        launch_pdl((const void*)cvt_all_kernel, dim3((C4_6 + 255) / 256), dim3(256), 0, args);
    }
    {
        const float *gA = enc_ln, *bA = enc_ln + D, *gB = dec_ln, *bB = dec_ln + D;
        void* args[] = {&src, &tgt, &tok_emb, &pos_emb, &gA, &bA, &gB, &bB,
                        &x, &x2, &hb, &hb2};
        launch_pdl((const void*)embed2_kernel, dim3(MROWS / 8, 2), dim3(256), 0, args);
    }

    // ================= encoder =================
    for (int i = 0; i < NL; i++) {
        const bf16*  W   = wp + OFF_EA + (size_t)i * 4 * DD;
        const float* Wb  = enc_attn_b + (size_t)i * 4 * D;
        const float* lnp = enc_ln + (size_t)i * 4 * D;

        G(hb, W, Wb, nullptr, qkv, MROWS, D, D, 0, 0, 1, 128, 3, 0, DD, D, MD);
        FL(fgrid, qkv, qkv + MD, qkv + 2 * MD, src, 0, aob);
        G32(aob, W + 3 * DD, Wb + 3 * D, x, x, MROWS, D, D, 0, 0);

        LN(x, lnp + 2 * D, lnp + 3 * D, hb);
        G2(0, dim3(FF / 128, MROWS / 128, 1),
           hb, wp + OFF_EF1 + (size_t)i * D * FF, enc_ffn_b1 + (size_t)i * FF,
           ffnb, MROWS, FF, D, 1, 0, 0, 0, 0, 0);
        G32(ffnb, wp + OFF_EF2 + (size_t)i * FF * D, enc_ffn_b2 + (size_t)i * D,
            x, x, MROWS, D, FF, 0, 0);
        if (i < NL - 1)
            LN(x, enc_ln + (size_t)(i + 1) * 4 * D, enc_ln + (size_t)(i + 1) * 4 * D + D, hb);
    }
    LN(x, enc_fln, enc_fln + D, memb);

    // cross-attention K/V for all decoder layers: single batch-12 launch
    G2(0, dim3(D / 128, MROWS / 128, 2 * NL),
       memb, wp + OFF_DA, dec_attn_b, kvc, MROWS, D, D, 0, 0, 0, 0, MD, 1);

    // ================= decoder =================
    for (int i = 0; i < NL; i++) {
        const bf16*  W   = wp + OFF_DA + (size_t)i * 8 * DD;
        const float* Wb  = dec_attn_b + (size_t)i * 8 * D;
        const float* lnp = dec_ln + (size_t)i * 6 * D;

        // self-attention
        G(hb2, W, Wb, nullptr, qkv, MROWS, D, D, 0, 0, 1, 128, 3, 0, DD, D, MD);
        FL(fgrid, qkv, qkv + MD, qkv + 2 * MD, tgt, 1, aob);
        G32(aob, W + 3 * DD, Wb + 3 * D, x2, x2, MROWS, D, D, 0, 0);

        // cross-attention
        LN(x2, lnp + 2 * D, lnp + 3 * D, hb2);
        G32(hb2, W + 4 * DD, Wb + 4 * D, nullptr, qkv, MROWS, D, D, 0, 1);
        FL(fgrid, qkv, kc + (size_t)i * MD, vc + (size_t)i * MD, src, 0, aob);
        G32(aob, W + 7 * DD, Wb + 7 * D, x2, x2, MROWS, D, D, 0, 0);

        // FFN
        LN(x2, lnp + 4 * D, lnp + 5 * D, hb2);
        G2(0, dim3(FF / 128, MROWS / 128, 1),
           hb2, wp + OFF_DF1 + (size_t)i * D * FF, dec_ffn_b1 + (size_t)i * FF,
           ffnb, MROWS, FF, D, 1, 0, 0, 0, 0, 0);
        G32(ffnb, wp + OFF_DF2 + (size_t)i * FF * D, dec_ffn_b2 + (size_t)i * D,
            x2, x2, MROWS, D, FF, 0, 0);
        if (i < NL - 1)
            LN(x2, dec_ln + (size_t)(i + 1) * 6 * D, dec_ln + (size_t)(i + 1) * 6 * D + D, hb2);
    }
    LN(x2, dec_fln, dec_fln + D, hb2);

    // ============ generator: tied projection + log_softmax ============
    G2(1, dim3(VV / 128, MROWS / 128, 1),
       hb2, wp + OFF_EMB, nullptr, out, MROWS, VV, D, 0, 0, 0, 0, 0, 0);
    {
        void* args[] = {&out};
        launch_pdl((const void*)logsoftmax_kernel, dim3(MROWS), dim3(512), LS_SMEM, args);
    }
}